// round 16
// baseline (speedup 1.0000x reference)
#include <cuda_runtime.h>
#include <cuda_bf16.h>
#include <math.h>

// ---------------- problem constants ----------------
#define BB 2
#define SS 2048
#define DD 1024
#define NHH 16
#define DHH 64
#define NIAFH 4
#define QKVD 1024
#define MLPD 4096
#define ZD 32
#define HIAFD 128
#define HIAFP 256              // padded hdn width for GEMM (N%256==0)
#define XAK 3072               // split-GEMM K: [x_hi | x_hi | x_lo]
#define RG 8
#define KVL (SS + RG)          // 2056
#define KVS 2080               // padded V stride
#define UPN (QKVD + 2*QKVD + 2*MLPD)   // 11264
#define UPK (DD + ZD)          // 1056
#define DWK (ZD + QKVD + MLPD) // 5152
#define NTOK (BB*SS)           // 4096

#define ZSCALE 0.04419417382415922f    // sqrt(1/(32*16))
#define SPSHIFT 0.5413248546129181f    // log(e-1)
#define NEGV -1000000000.0f

// output layout: h_out | z | mu | sigma
#define OFF_Z  (NTOK*DD)
#define OFF_MU (OFF_Z + NTOK*ZD)
#define OFF_SG (OFF_MU + NTOK*ZD)

// ---------------- scratch ----------------
__device__ __nv_bfloat16 g_xz_b[(size_t)NTOK*UPK];     // [x | z] bf16
__device__ __nv_bfloat16 g_u_b[(size_t)NTOK*UPN];      // up-proj out bf16 (qkv cols only)
__device__ __nv_bfloat16 g_down_b[(size_t)NTOK*DWK];   // [z|attn|mlp] bf16
__device__ __nv_bfloat16 g_upw_b[(size_t)UPN*UPK];     // bf16 up weights (mlp rows interleaved)
__device__ __nv_bfloat16 g_dnw_b[(size_t)DD*DWK];      // bf16 down weights
__device__ __nv_bfloat16 g_xa[(size_t)NTOK*XAK];       // [x_hi | x_hi | x_lo]
__device__ __nv_bfloat16 g_wxs[(size_t)HIAFP*XAK];     // [w_hi | w_lo | w_hi] (pad rows 0)
__device__ float        g_hdnp[(size_t)NTOK*HIAFP];    // hdn pre-activation fp32
__device__ __nv_bfloat16 g_Qb[(size_t)BB*NHH*SS*DHH];  // roped Q bf16
__device__ __nv_bfloat16 g_Kb[(size_t)BB*NHH*KVL*DHH]; // registers + roped K bf16
__device__ __nv_bfloat16 g_Vb[(size_t)BB*NHH*KVS*DHH]; // registers + V bf16 (pad zero)
__device__ int   g_mask_mode;

struct RopeTab { float inv[32]; };

// ---------------- mma helpers ----------------
__device__ __forceinline__ void mma16bf(float* d, const unsigned* a, const unsigned* b) {
    asm volatile(
        "mma.sync.aligned.m16n8k16.row.col.f32.bf16.bf16.f32 "
        "{%0,%1,%2,%3}, {%4,%5,%6,%7}, {%8,%9}, {%0,%1,%2,%3};"
        : "+f"(d[0]), "+f"(d[1]), "+f"(d[2]), "+f"(d[3])
        : "r"(a[0]), "r"(a[1]), "r"(a[2]), "r"(a[3]), "r"(b[0]), "r"(b[1]));
}
__device__ __forceinline__ unsigned pack_bf(float a, float b) {
    __nv_bfloat162 h = __floats2bfloat162_rn(a, b);
    return *(unsigned*)&h;
}
__device__ __forceinline__ unsigned smem_u32(const void* p) {
    return (unsigned)__cvta_generic_to_shared(p);
}
__device__ __forceinline__ void ldmx4(unsigned* r, const __nv_bfloat16* base) {
    unsigned a = smem_u32(base);
    asm volatile("ldmatrix.sync.aligned.m8n8.x4.shared.b16 {%0,%1,%2,%3}, [%4];"
        : "=r"(r[0]), "=r"(r[1]), "=r"(r[2]), "=r"(r[3]) : "r"(a));
}

// =======================================================================
// Kernel 0: classify the storage dtype of the bool `mask` input.
// =======================================================================
__global__ void detect_mask_kernel(const unsigned char* __restrict__ p)
{
    if (threadIdx.x != 0 || blockIdx.x != 0) return;
    const unsigned int* w = (const unsigned int*)p;
    bool allf = true, anyf = false, i32ok = true;
    for (int i = 0; i < 1024; i++) {
        unsigned int v = w[i];
        if (v == 0x3F800000u) anyf = true;
        else if (v != 0u) allf = false;
        if ((v & 0xFFFFFF00u) != 0u) i32ok = false;
    }
    g_mask_mode = (allf && anyf) ? 2 : (i32ok ? 1 : 0);
}

__device__ __forceinline__ float read_mask(const unsigned char* p, int m, int mode)
{
    if (mode == 1) return ((const int*)p)[m] != 0 ? 1.f : 0.f;
    if (mode == 2) return ((const float*)p)[m] != 0.f ? 1.f : 0.f;
    return p[m] != 0 ? 1.f : 0.f;
}

// =======================================================================
// Kernel 0b: conversions
// =======================================================================
__global__ void convert_bf16_kernel(const float* __restrict__ src,
                                    __nv_bfloat16* __restrict__ dst, int n2)
{
    int i = blockIdx.x*256 + threadIdx.x;
    if (i < n2) {
        float2 v = ((const float2*)src)[i];
        ((__nv_bfloat162*)dst)[i] = __floats2bfloat162_rn(v.x, v.y);
    }
}

// up_w conversion with MLP gate/val row interleave:
//   r < 3*QKVD            -> row r
//   gate j (r=3Q+j)       -> row 3Q + 2j
//   val  j (r=3Q+MLPD+j)  -> row 3Q + 2j + 1
__global__ void convert_upw_kernel(const float* __restrict__ src)
{
    int i = blockIdx.x*256 + threadIdx.x;   // over UPN * (UPK/2)
    if (i >= UPN*(UPK/2)) return;
    int r = i / (UPK/2), kp = i - (i / (UPK/2))*(UPK/2);
    int rd;
    if (r < 3*QKVD) rd = r;
    else if (r < 3*QKVD + MLPD) rd = 3*QKVD + 2*(r - 3*QKVD);
    else rd = 3*QKVD + 2*(r - 3*QKVD - MLPD) + 1;
    float2 v = ((const float2*)(src + (size_t)r*UPK))[kp];
    ((__nv_bfloat162*)(g_upw_b + (size_t)rd*UPK))[kp] = __floats2bfloat162_rn(v.x, v.y);
}

// iaf_wx split: g_wxs[j][0..1023]=w_hi, [1024..2047]=w_lo, [2048..3071]=w_hi
__global__ void convert_wxs_kernel(const float* __restrict__ wx)
{
    int idx = blockIdx.x*256 + threadIdx.x;      // over HIAFP*DD
    if (idx >= HIAFP*DD) return;
    int j = idx >> 10, d = idx & 1023;
    __nv_bfloat16 hi, lo;
    if (j < HIAFD) {
        float w = wx[(size_t)j*DD + d];
        hi = __float2bfloat16(w);
        lo = __float2bfloat16(w - __bfloat162float(hi));
    } else {
        hi = __float2bfloat16(0.f);
        lo = __float2bfloat16(0.f);
    }
    __nv_bfloat16* row = g_wxs + (size_t)j*XAK;
    row[d] = hi;
    row[1024 + d] = lo;
    row[2048 + d] = hi;
}

// =======================================================================
// Kernel 1a: LayerNorm per token -> bf16 x (+ split hi/lo into g_xa)
// =======================================================================
__global__ void __launch_bounds__(128) ln_kernel(
    const float* __restrict__ hs,
    const float* __restrict__ ln_w, const float* __restrict__ ln_b)
{
    __shared__ float redS[4], redQ[4], stat[2];
    const int tid = threadIdx.x, lane = tid & 31, wid = tid >> 5;
    const int m = blockIdx.x;
    const float* hp = hs + (size_t)m*DD;

    float4 xv[2];
    float s = 0.f, q = 0.f;
    #pragma unroll
    for (int k = 0; k < 2; k++) {
        xv[k] = *(const float4*)(hp + tid*4 + k*512);
        s += xv[k].x + xv[k].y + xv[k].z + xv[k].w;
        q += xv[k].x*xv[k].x + xv[k].y*xv[k].y + xv[k].z*xv[k].z + xv[k].w*xv[k].w;
    }
    #pragma unroll
    for (int o = 16; o; o >>= 1) {
        s += __shfl_down_sync(0xffffffffu, s, o);
        q += __shfl_down_sync(0xffffffffu, q, o);
    }
    if (lane == 0) { redS[wid] = s; redQ[wid] = q; }
    __syncthreads();
    if (tid == 0) {
        float S1 = redS[0]+redS[1]+redS[2]+redS[3];
        float Q1 = redQ[0]+redQ[1]+redQ[2]+redQ[3];
        float mean = S1 / (float)DD;
        float var  = Q1 / (float)DD - mean*mean;
        stat[0] = mean;
        stat[1] = rsqrtf(var + 1e-5f);
    }
    __syncthreads();
    float mean = stat[0], rstd = stat[1];
    __nv_bfloat16* xzr = g_xz_b + (size_t)m*UPK;
    __nv_bfloat16* xar = g_xa + (size_t)m*XAK;
    #pragma unroll
    for (int k = 0; k < 2; k++) {
        int d = tid*4 + k*512;
        float4 wv = *(const float4*)(ln_w + d);
        float4 bv = *(const float4*)(ln_b + d);
        float xf[4];
        xf[0] = (xv[k].x - mean)*rstd*wv.x + bv.x;
        xf[1] = (xv[k].y - mean)*rstd*wv.y + bv.y;
        xf[2] = (xv[k].z - mean)*rstd*wv.z + bv.z;
        xf[3] = (xv[k].w - mean)*rstd*wv.w + bv.w;
        #pragma unroll
        for (int e = 0; e < 4; e++) {
            __nv_bfloat16 hi = __float2bfloat16(xf[e]);
            __nv_bfloat16 lo = __float2bfloat16(xf[e] - __bfloat162float(hi));
            xzr[d + e] = hi;
            xar[d + e] = hi;
            xar[1024 + d + e] = hi;
            xar[2048 + d + e] = lo;
        }
    }
}

// =======================================================================
// Kernel 1b: z/mu/sigma from fp32 hdn-pre + noise terms (8 tokens/block)
// =======================================================================
__global__ void __launch_bounds__(128) z_kernel(
    const unsigned char* __restrict__ mask, const float* __restrict__ noise,
    const float* __restrict__ iaf_wn, const float* __restrict__ iaf_w2,
    float* __restrict__ out)
{
    __shared__ float ns[8][ZD];
    __shared__ float hdn[8][HIAFD];
    __shared__ float zps[8][2*ZD];
    __shared__ float fmv[8];
    const int tid = threadIdx.x;
    const int m0 = blockIdx.x * 8;
    const int mmode = g_mask_mode;

    {
        int t = tid >> 5, i = tid & 31;
        float fm = read_mask(mask, m0 + t, mmode);
        ns[t][i] = noise[(size_t)(m0 + t)*ZD + i] * fm;
        ns[t + 4][i] = noise[(size_t)(m0 + t + 4)*ZD + i] *
                       read_mask(mask, m0 + t + 4, mmode);
        if (i == 0) {
            fmv[t] = fm;
            fmv[t + 4] = read_mask(mask, m0 + t + 4, mmode);
        }
    }
    __syncthreads();

    {
        int j = tid;
        float acc[8];
        #pragma unroll
        for (int t = 0; t < 8; t++)
            acc[t] = g_hdnp[(size_t)(m0 + t)*HIAFP + j];
        int dm = j % 31;                 // M1[j][i] = (i <= j%31)
        const float* wn = iaf_wn + (size_t)j*ZD;
        for (int i = 0; i <= dm; i++) {
            float w = wn[i];
            #pragma unroll
            for (int t = 0; t < 8; t++) acc[t] += ns[t][i]*w;
        }
        #pragma unroll
        for (int t = 0; t < 8; t++) {
            float v = acc[t];
            hdn[t][j] = v / (1.f + __expf(-v));
        }
    }
    __syncthreads();

    if (tid < 64) {
        int o = tid, lim = o & 31;       // M2[o][j] = (j%31 < o%32)
        float acc[8];
        #pragma unroll
        for (int t = 0; t < 8; t++) acc[t] = 0.f;
        const float* w2 = iaf_w2 + (size_t)o*HIAFD;
        for (int j = 0; j < HIAFD; j++) {
            if ((j % 31) < lim) {
                float w = w2[j];
                #pragma unroll
                for (int t = 0; t < 8; t++) acc[t] += hdn[t][j]*w;
            }
        }
        #pragma unroll
        for (int t = 0; t < 8; t++) zps[t][o] = fmv[t]*ZSCALE*acc[t];
    }
    __syncthreads();

    for (int idx = tid; idx < 8*ZD; idx += 128) {
        int t = idx >> 5, i = idx & 31;
        int m = m0 + t;
        float mu = zps[t][i];
        float ls = zps[t][ZD + i] + SPSHIFT;
        float sg = (ls > 20.f) ? ls : log1pf(expf(ls));
        float z  = mu + sg*ns[t][i];
        g_xz_b[(size_t)m*UPK + DD + i] = __float2bfloat16(z);
        g_down_b[(size_t)m*DWK + i]    = __float2bfloat16(z);
        out[OFF_Z  + (size_t)m*ZD + i] = z;
        out[OFF_MU + (size_t)m*ZD + i] = mu;
        out[OFF_SG + (size_t)m*ZD + i] = sg;
    }
}

// =======================================================================
// Kernel 2: BF16 GEMM 128x256x32, cp.async double-buffered, ldmatrix frags.
//   EPI=0: C bf16;  EPI=1: C fp32 residual;  EPI=2: C fp32 plain;
//   EPI=3: cols<3*QKVD -> bf16 into g_u; cols>=3*QKVD (gate/val interleave)
//          -> silu(gate)*val bf16 into g_down_b.
// =======================================================================
#define APITCH 40

__device__ __forceinline__ void bgemm_prefetch(
    const __nv_bfloat16* __restrict__ A, const __nv_bfloat16* __restrict__ B,
    __nv_bfloat16* As, __nv_bfloat16* Bs, int bm, int bn, int lda, int ldb, int k0, int tid)
{
    #pragma unroll
    for (int j = 0; j < 2; j++) {
        int idx = tid + j*256, r = idx >> 2, c = idx & 3;
        unsigned d = smem_u32(As + r*APITCH + c*8);
        asm volatile("cp.async.ca.shared.global [%0], [%1], 16;"
                     :: "r"(d), "l"(A + (size_t)(bm + r)*lda + k0 + c*8));
    }
    #pragma unroll
    for (int j = 0; j < 4; j++) {
        int idx = tid + j*256, r = idx >> 2, c = idx & 3;
        unsigned d = smem_u32(Bs + r*APITCH + c*8);
        asm volatile("cp.async.ca.shared.global [%0], [%1], 16;"
                     :: "r"(d), "l"(B + (size_t)(bn + r)*ldb + k0 + c*8));
    }
}

template<int EPI>
__global__ void __launch_bounds__(256) bf16_gemm_nt(
    const __nv_bfloat16* __restrict__ A, const __nv_bfloat16* __restrict__ Bw, void* Cp,
    int M, int N, int K, int lda, int ldb,
    const float* __restrict__ addsrc, const float* __restrict__ alphap)
{
    extern __shared__ __nv_bfloat16 smb[];
    __nv_bfloat16* Asb[2] = { smb, smb + 128*APITCH };
    __nv_bfloat16* Bsb[2] = { smb + 2*128*APITCH, smb + 2*128*APITCH + 256*APITCH };
    const int tid = threadIdx.x;
    const int lane = tid & 31, wid = tid >> 5;
    const int g = lane >> 2, t = lane & 3;
    const int l16 = lane & 15, lhi = (lane >> 4) * 8;
    const int wm = (wid >> 2) * 64, wn = (wid & 3) * 64;
    const int bm = blockIdx.y * 128, bn = blockIdx.x * 256;

    float acc[4][8][4];
    #pragma unroll
    for (int mi = 0; mi < 4; mi++)
        #pragma unroll
        for (int ni = 0; ni < 8; ni++)
            #pragma unroll
            for (int e = 0; e < 4; e++) acc[mi][ni][e] = 0.f;

    const int KT = K / 32;
    bgemm_prefetch(A, Bw, Asb[0], Bsb[0], bm, bn, lda, ldb, 0, tid);
    asm volatile("cp.async.commit_group;");

    for (int kt = 0; kt < KT; kt++) {
        const int buf = kt & 1;
        if (kt + 1 < KT) {
            bgemm_prefetch(A, Bw, Asb[buf^1], Bsb[buf^1], bm, bn, lda, ldb, (kt+1)*32, tid);
            asm volatile("cp.async.commit_group;");
            asm volatile("cp.async.wait_group 1;");
        } else {
            asm volatile("cp.async.wait_group 0;");
        }
        __syncthreads();
        const __nv_bfloat16* As = Asb[buf];
        const __nv_bfloat16* Bs = Bsb[buf];
        #pragma unroll
        for (int ks = 0; ks < 32; ks += 16) {
            unsigned a[4][4], b[8][2];
            #pragma unroll
            for (int mi = 0; mi < 4; mi++)
                ldmx4(a[mi], As + (wm + mi*16 + l16)*APITCH + ks + lhi);
            #pragma unroll
            for (int np = 0; np < 4; np++) {
                unsigned r[4];
                ldmx4(r, Bs + (wn + np*16 + l16)*APITCH + ks + lhi);
                b[2*np][0] = r[0]; b[2*np + 1][0] = r[1];
                b[2*np][1] = r[2]; b[2*np + 1][1] = r[3];
            }
            #pragma unroll
            for (int mi = 0; mi < 4; mi++)
                #pragma unroll
                for (int ni = 0; ni < 8; ni++)
                    mma16bf(acc[mi][ni], a[mi], b[ni]);
        }
        __syncthreads();
    }

    float alpha = (EPI == 1) ? *alphap : 0.f;
    #pragma unroll
    for (int mi = 0; mi < 4; mi++) {
        int r0 = bm + wm + mi*16 + g;
        #pragma unroll
        for (int ni = 0; ni < 8; ni++) {
            int c0 = bn + wn + ni*8 + 2*t;
            #pragma unroll
            for (int h = 0; h < 2; h++) {
                int row = r0 + 8*h;
                float v0 = acc[mi][ni][2*h], v1 = acc[mi][ni][2*h + 1];
                if (EPI == 1) {
                    size_t o = (size_t)row*N + c0;
                    float* C = (float*)Cp;
                    C[o]   = addsrc[o]   + alpha*v0;
                    C[o+1] = addsrc[o+1] + alpha*v1;
                } else if (EPI == 2) {
                    size_t o = (size_t)row*N + c0;
                    float* C = (float*)Cp;
                    C[o]   = v0;
                    C[o+1] = v1;
                } else if (EPI == 3) {
                    if (c0 < 3*QKVD) {
                        __nv_bfloat16* C = (__nv_bfloat16*)Cp;
                        *(__nv_bfloat162*)(C + (size_t)row*UPN + c0) =
                            __floats2bfloat162_rn(v0, v1);
                    } else {
                        int j = (c0 - 3*QKVD) >> 1;      // v0=gate, v1=val
                        float r = v0 / (1.f + __expf(-v0)) * v1;
                        g_down_b[(size_t)row*DWK + ZD + QKVD + j] = __float2bfloat16(r);
                    }
                } else {
                    size_t o = (size_t)row*N + c0;
                    __nv_bfloat16* C = (__nv_bfloat16*)Cp;
                    *(__nv_bfloat162*)(C + o) = __floats2bfloat162_rn(v0, v1);
                }
            }
        }
    }
}

// =======================================================================
// Kernel 3: QKV prep — 8 tokens/block, bf16 u reads, RoPE, bf16 QKV out
// =======================================================================
__global__ void __launch_bounds__(256) prep_qkv(
    const float* __restrict__ next_noise, const float* __restrict__ iaf_up_w, RopeTab tab)
{
    __shared__ float nn[8][ZD];
    __shared__ float kadds[8][256], vadds[8][256];
    const int tid = threadIdx.x;
    const int m0 = blockIdx.x * 8;

    {
        int t8 = tid >> 5, i = tid & 31;
        nn[t8][i] = next_noise[(size_t)(m0 + t8)*ZD + i];
    }
    __syncthreads();
    {
        const float* wk = iaf_up_w + (size_t)tid*ZD;
        const float* wv = iaf_up_w + (size_t)(QKVD + tid)*ZD;
        float ka[8], va[8];
        #pragma unroll
        for (int u = 0; u < 8; u++) { ka[u] = 0.f; va[u] = 0.f; }
        #pragma unroll 4
        for (int i = 0; i < ZD; i++) {
            float wki = wk[i], wvi = wv[i];
            #pragma unroll
            for (int u = 0; u < 8; u++) {
                ka[u] += nn[u][i]*wki;
                va[u] += nn[u][i]*wvi;
            }
        }
        #pragma unroll
        for (int u = 0; u < 8; u++) { kadds[u][tid] = ka[u]; vadds[u][tid] = va[u]; }
    }
    __syncthreads();

    const int dd = tid & 31;
    for (int u = 0; u < 8; u++) {
        int m = m0 + u;
        int b = m >> 11, spos = m & 2047;
        const __nv_bfloat16* um = g_u_b + (size_t)m*UPN;
        float ang = (float)spos * tab.inv[dd];
        float c, sn; sincosf(ang, &sn, &c);
        #pragma unroll
        for (int pp = 0; pp < 2; pp++) {
            int p = tid + pp*256;            // 0..511
            int hh = p >> 5;
            int i1 = hh*DHH + dd, i2 = i1 + 32;
            float q1 = __bfloat162float(um[i1]);
            float q2 = __bfloat162float(um[i2]);
            size_t qo = (((size_t)(b*NHH + hh))*SS + spos)*DHH;
            g_Qb[qo + dd]      = __float2bfloat16(q1*c - q2*sn);
            g_Qb[qo + 32 + dd] = __float2bfloat16(q2*c + q1*sn);
            float k1 = __bfloat162float(um[QKVD + i1]) + (i1 < 256 ? kadds[u][i1] : 0.f);
            float k2 = __bfloat162float(um[QKVD + i2]) + (i2 < 256 ? kadds[u][i2] : 0.f);
            size_t ko = (((size_t)(b*NHH + hh))*KVL + RG + spos)*DHH;
            g_Kb[ko + dd]      = __float2bfloat16(k1*c - k2*sn);
            g_Kb[ko + 32 + dd] = __float2bfloat16(k2*c + k1*sn);
        }
        #pragma unroll
        for (int pp = 0; pp < 4; pp++) {
            int p = tid + pp*256;            // 0..1023
            int hh = p >> 6;
            float vv = __bfloat162float(um[2*QKVD + p]) + (p < 256 ? vadds[u][p] : 0.f);
            g_Vb[(((size_t)(b*NHH + hh))*KVS + RG + spos)*DHH + (p & 63)] = __float2bfloat16(vv);
        }
    }
}

// register tokens K/V fill + V pad-row zeroing
__global__ void regfill_kernel(const float* __restrict__ reg_k, const float* __restrict__ reg_v)
{
    int bh = blockIdx.x, hh = bh & 15;
    int j = threadIdx.x >> 6, d = threadIdx.x & 63;
    g_Kb[((size_t)bh*KVL + j)*DHH + d] = __float2bfloat16(reg_k[((size_t)j*NHH + hh)*DHH + d]);
    g_Vb[((size_t)bh*KVS + j)*DHH + d] = __float2bfloat16(reg_v[((size_t)j*NHH + hh)*DHH + d]);
    for (int idx = threadIdx.x; idx < (KVS - KVL)*DHH; idx += blockDim.x)
        g_Vb[((size_t)bh*KVS + KVL)*DHH + idx] = __float2bfloat16(0.f);
}

// =======================================================================
// Kernel 4: FLASH attention, all-bf16 mma (m16n8k16), no P shuffles
// =======================================================================
#define KSPb 72     // Ks pitch (bf16), rows = q/k tokens
#define VSPb 134    // Vs pitch (bf16), rows = head dim (n-major, transposed)
#define FLASH_SMEM (128*KSPb*2 + 64*VSPb*2)   // 35584 B

__global__ void __launch_bounds__(256) flash_kernel(const float* __restrict__ attn_mask)
{
    extern __shared__ __nv_bfloat16 sfb[];
    __nv_bfloat16* Ks = sfb;
    __nv_bfloat16* Vs = sfb + 128*KSPb;
    const int tid = threadIdx.x, lane = tid & 31, w = tid >> 5;
    const int g = lane >> 2, t = lane & 3;
    const int bh = blockIdx.y, b = bh >> 4, hh = bh & 15;
    const int bm = blockIdx.x * 128;
    const __nv_bfloat16* Qb = g_Qb + (size_t)bh*SS*DHH;
    const __nv_bfloat16* Kb = g_Kb + (size_t)bh*KVL*DHH;
    const __nv_bfloat16* Vb = g_Vb + (size_t)bh*KVS*DHH;

    // stage Q tile (bf16 copy), gather bf16 A-frags
    #pragma unroll
    for (int j = 0; j < 4; j++) {
        int idx = tid + j*256, r = idx >> 3, c8 = (idx & 7)*8;
        *(uint4*)(Ks + r*KSPb + c8) = *(const uint4*)(Qb + (size_t)(bm + r)*DHH + c8);
    }
    __syncthreads();
    unsigned aQ[4][4];
    #pragma unroll
    for (int ks = 0; ks < 4; ks++) {
        const __nv_bfloat16* p0 = Ks + (w*16 + g)*KSPb + ks*16 + 2*t;
        aQ[ks][0] = *(const unsigned*)(p0);
        aQ[ks][1] = *(const unsigned*)(p0 + 8*KSPb);
        aQ[ks][2] = *(const unsigned*)(p0 + 8);
        aQ[ks][3] = *(const unsigned*)(p0 + 8*KSPb + 8);
    }
    __syncthreads();

    float accO[8][4];
    #pragma unroll
    for (int vn = 0; vn < 8; vn++)
        #pragma unroll
        for (int e = 0; e < 4; e++) accO[vn][e] = 0.f;
    float mrow0 = -1e30f, mrow1 = -1e30f, lrow0 = 0.f, lrow1 = 0.f;

    const int gi0 = bm + w*16 + g, gi1 = gi0 + 8;
    const float* am0 = attn_mask + ((size_t)b*SS + gi0)*SS;
    const float* am1 = attn_mask + ((size_t)b*SS + gi1)*SS;
    const bool iafh = (hh < NIAFH);

    for (int j0 = 0; j0 < KVL; j0 += 128) {
        #pragma unroll
        for (int j = 0; j < 4; j++) {
            int idx = tid + j*256, r = idx >> 3, c8 = (idx & 7)*8;
            uint4 v = (j0 + r < KVL)
                    ? *(const uint4*)(Kb + (size_t)(j0 + r)*DHH + c8)
                    : make_uint4(0u, 0u, 0u, 0u);
            *(uint4*)(Ks + r*KSPb + c8) = v;
        }
        #pragma unroll
        for (int j = 0; j < 4; j++) {
            int idx = tid + j*256, r = idx >> 3, c8 = (idx & 7)*8;
            uint4 v = (j0 + r < KVL)
                    ? *(const uint4*)(Vb + (size_t)(j0 + r)*DHH + c8)
                    : make_uint4(0u, 0u, 0u, 0u);
            __nv_bfloat16 h[8];
            *(uint4*)h = v;
            #pragma unroll
            for (int i = 0; i < 8; i++)
                Vs[(c8 + i)*VSPb + r] = h[i];
        }
        __syncthreads();

        float s[16][4];
        #pragma unroll
        for (int nt = 0; nt < 16; nt++)
            #pragma unroll
            for (int e = 0; e < 4; e++) s[nt][e] = 0.f;
        #pragma unroll
        for (int ks = 0; ks < 4; ks++) {
            #pragma unroll
            for (int nt = 0; nt < 16; nt++) {
                unsigned bb[2];
                const __nv_bfloat16* pn = Ks + (nt*8 + g)*KSPb + ks*16 + 2*t;
                bb[0] = *(const unsigned*)(pn);
                bb[1] = *(const unsigned*)(pn + 8);
                mma16bf(s[nt], aQ[ks], bb);
            }
        }

        float tmax0 = -1e30f, tmax1 = -1e30f;
        #pragma unroll
        for (int nt = 0; nt < 16; nt++) {
            int colbase = j0 + nt*8;
            if (colbase >= KVL) {
                s[nt][0] = s[nt][1] = s[nt][2] = s[nt][3] = -1e30f;
            } else if (colbase < RG) {
                s[nt][0] *= 0.125f; s[nt][1] *= 0.125f;
                s[nt][2] *= 0.125f; s[nt][3] *= 0.125f;
            } else {
                int js = colbase + 2*t - RG;
                float2 a0 = *(const float2*)(am0 + js);
                float2 a1 = *(const float2*)(am1 + js);
                float mk00 = a0.x, mk01 = a0.y, mk10 = a1.x, mk11 = a1.y;
                if (iafh) {
                    if (js     >= gi0) mk00 += NEGV;
                    if (js + 1 >= gi0) mk01 += NEGV;
                    if (js     >= gi1) mk10 += NEGV;
                    if (js + 1 >= gi1) mk11 += NEGV;
                }
                s[nt][0] = s[nt][0]*0.125f + mk00;
                s[nt][1] = s[nt][1]*0.125f + mk01;
                s[nt][2] = s[nt][2]*0.125f + mk10;
                s[nt][3] = s[nt][3]*0.125f + mk11;
            }
            tmax0 = fmaxf(tmax0, fmaxf(s[nt][0], s[nt][1]));
            tmax1 = fmaxf(tmax1, fmaxf(s[nt][2], s[nt][3]));
        }
        tmax0 = fmaxf(tmax0, __shfl_xor_sync(0xffffffffu, tmax0, 1));
        tmax0 = fmaxf(tmax0, __shfl_xor_sync(0xffffffffu, tmax0, 2));
        tmax1 = fmaxf(tmax1, __shfl_xor_sync(0xffffffffu, tmax1, 1));
        tmax1 = fmaxf(tmax1, __shfl_xor_sync(0xffffffffu, tmax1, 2));

        float newm0 = fmaxf(mrow0, tmax0);
        float newm1 = fmaxf(mrow1, tmax1);
        float sc0 = __expf(mrow0 - newm0);
        float sc1 = __expf(mrow1 - newm1);
        float rs0 = 0.f, rs1 = 0.f;
        #pragma unroll
        for (int nt = 0; nt < 16; nt++) {
            float p0 = __expf(s[nt][0] - newm0);
            float p1 = __expf(s[nt][1] - newm0);
            float p2 = __expf(s[nt][2] - newm1);
            float p3 = __expf(s[nt][3] - newm1);
            s[nt][0] = p0; s[nt][1] = p1; s[nt][2] = p2; s[nt][3] = p3;
            rs0 += p0 + p1; rs1 += p2 + p3;
        }
        rs0 += __shfl_xor_sync(0xffffffffu, rs0, 1);
        rs0 += __shfl_xor_sync(0xffffffffu, rs0, 2);
        rs1 += __shfl_xor_sync(0xffffffffu, rs1, 1);
        rs1 += __shfl_xor_sync(0xffffffffu, rs1, 2);
        lrow0 = lrow0*sc0 + rs0;
        lrow1 = lrow1*sc1 + rs1;
        mrow0 = newm0; mrow1 = newm1;
        #pragma unroll
        for (int vn = 0; vn < 8; vn++) {
            accO[vn][0] *= sc0; accO[vn][1] *= sc0;
            accO[vn][2] *= sc1; accO[vn][3] *= sc1;
        }

        #pragma unroll
        for (int ks = 0; ks < 8; ks++) {
            unsigned aP[4];
            aP[0] = pack_bf(s[2*ks][0],     s[2*ks][1]);
            aP[1] = pack_bf(s[2*ks][2],     s[2*ks][3]);
            aP[2] = pack_bf(s[2*ks + 1][0], s[2*ks + 1][1]);
            aP[3] = pack_bf(s[2*ks + 1][2], s[2*ks + 1][3]);
            #pragma unroll
            for (int vn = 0; vn < 8; vn++) {
                unsigned bb[2];
                const __nv_bfloat16* pv = Vs + (vn*8 + g)*VSPb + ks*16 + 2*t;
                bb[0] = *(const unsigned*)(pv);
                bb[1] = *(const unsigned*)(pv + 8);
                mma16bf(accO[vn], aP, bb);
            }
        }
        __syncthreads();
    }

    float inv0 = 1.f / lrow0, inv1 = 1.f / lrow1;
    int row0 = b*SS + gi0, row1 = b*SS + gi1;
    #pragma unroll
    for (int vn = 0; vn < 8; vn++) {
        int n = vn*8 + 2*t;
        *(__nv_bfloat162*)(g_down_b + (size_t)row0*DWK + ZD + hh*DHH + n) =
            __floats2bfloat162_rn(accO[vn][0]*inv0, accO[vn][1]*inv0);
        *(__nv_bfloat162*)(g_down_b + (size_t)row1*DWK + ZD + hh*DHH + n) =
            __floats2bfloat162_rn(accO[vn][2]*inv1, accO[vn][3]*inv1);
    }
}

// =======================================================================
// launch
// =======================================================================
extern "C" void kernel_launch(void* const* d_in, const int* in_sizes, int n_in,
                              void* d_out, int out_size)
{
    const float* hs          = (const float*)d_in[0];
    const unsigned char* msk = (const unsigned char*)d_in[1];
    const float* noise       = (const float*)d_in[2];
    const float* next_noise  = (const float*)d_in[3];
    const float* attn_mask   = (const float*)d_in[4];
    const float* ln_w        = (const float*)d_in[5];
    const float* ln_b        = (const float*)d_in[6];
    const float* alpha       = (const float*)d_in[7];
    const float* iaf_wx      = (const float*)d_in[8];
    const float* iaf_wn      = (const float*)d_in[9];
    const float* iaf_w2      = (const float*)d_in[10];
    const float* up_w        = (const float*)d_in[11];
    const float* iaf_up_w    = (const float*)d_in[12];
    const float* down_w      = (const float*)d_in[13];
    const float* reg_k       = (const float*)d_in[14];
    const float* reg_v       = (const float*)d_in[15];
    float* out = (float*)d_out;

    __nv_bfloat16 *p_xz, *p_u, *p_down, *p_dnw, *p_xa, *p_wxs;
    float *p_hdnp;
    cudaGetSymbolAddress((void**)&p_xz, g_xz_b);
    cudaGetSymbolAddress((void**)&p_u, g_u_b);
    cudaGetSymbolAddress((void**)&p_down, g_down_b);
    cudaGetSymbolAddress((void**)&p_dnw, g_dnw_b);
    cudaGetSymbolAddress((void**)&p_xa, g_xa);
    cudaGetSymbolAddress((void**)&p_wxs, g_wxs);
    cudaGetSymbolAddress((void**)&p_hdnp, g_hdnp);
    __nv_bfloat16 *p_upw;
    cudaGetSymbolAddress((void**)&p_upw, g_upw_b);

    const int GEMM_SMEM = (2*128 + 2*256)*APITCH*2;   // 61440
    (void)cudaFuncSetAttribute(bf16_gemm_nt<1>, cudaFuncAttributeMaxDynamicSharedMemorySize, GEMM_SMEM);
    (void)cudaFuncSetAttribute(bf16_gemm_nt<2>, cudaFuncAttributeMaxDynamicSharedMemorySize, GEMM_SMEM);
    (void)cudaFuncSetAttribute(bf16_gemm_nt<3>, cudaFuncAttributeMaxDynamicSharedMemorySize, GEMM_SMEM);
    (void)cudaFuncSetAttribute(flash_kernel, cudaFuncAttributeMaxDynamicSharedMemorySize, FLASH_SMEM);

    RopeTab rt;
    for (int d = 0; d < 32; d++) {
        float pw = powf(10000.f, (float)(2*d) / 64.f);
        rt.inv[d] = 1.f / pw;
    }

    detect_mask_kernel<<<1, 32>>>(msk);

    // weight conversions (fp32 -> bf16)
    convert_upw_kernel<<<(UPN*(UPK/2) + 255)/256, 256>>>(up_w);
    convert_bf16_kernel<<<(DD*DWK/2 + 255)/256, 256>>>(down_w, p_dnw, DD*DWK/2);
    convert_wxs_kernel<<<(HIAFP*DD + 255)/256, 256>>>(iaf_wx);

    // token path: LN -> split-precision iaf_wx GEMM (fp32 out) -> z/mu/sigma
    ln_kernel<<<NTOK, 128>>>(hs, ln_w, ln_b);
    bf16_gemm_nt<2><<<dim3(HIAFP/256, NTOK/128), 256, GEMM_SMEM>>>(
        p_xa, p_wxs, p_hdnp, NTOK, HIAFP, XAK, XAK, XAK, nullptr, nullptr);
    z_kernel<<<NTOK/8, 128>>>(msk, noise, iaf_wn, iaf_w2, out);

    // up-GEMM with fused SiLU-MLP epilogue (gate/val interleaved weights)
    bf16_gemm_nt<3><<<dim3(UPN/256, NTOK/128), 256, GEMM_SMEM>>>(
        p_xz, p_upw, p_u, NTOK, UPN, UPK, UPK, UPK, nullptr, nullptr);

    prep_qkv<<<NTOK/8, 256>>>(next_noise, iaf_up_w, rt);
    regfill_kernel<<<BB*NHH, 512>>>(reg_k, reg_v);

    flash_kernel<<<dim3(SS/128, BB*NHH), 256, FLASH_SMEM>>>(attn_mask);

    bf16_gemm_nt<1><<<dim3(DD/256, NTOK/128), 256, GEMM_SMEM>>>(
        p_down, p_dnw, out, NTOK, DD, DWK, DWK, DWK, hs, alpha);
}

// round 17
// speedup vs baseline: 1.0037x; 1.0037x over previous
#include <cuda_runtime.h>
#include <cuda_bf16.h>
#include <math.h>

// ---------------- problem constants ----------------
#define BB 2
#define SS 2048
#define DD 1024
#define NHH 16
#define DHH 64
#define NIAFH 4
#define QKVD 1024
#define MLPD 4096
#define ZD 32
#define HIAFD 128
#define HIAFP 256              // padded hdn width for GEMM (N%256==0)
#define XAK 3072               // split-GEMM K: [x_hi | x_hi | x_lo]
#define RG 8
#define KVL (SS + RG)          // 2056
#define KVS 2080               // padded V stride
#define UPN (QKVD + 2*QKVD + 2*MLPD)   // 11264
#define UPK (DD + ZD)          // 1056
#define DWK (ZD + QKVD + MLPD) // 5152
#define NTOK (BB*SS)           // 4096

#define ZSCALE 0.04419417382415922f    // sqrt(1/(32*16))
#define SPSHIFT 0.5413248546129181f    // log(e-1)
#define NEGV -1000000000.0f

// output layout: h_out | z | mu | sigma
#define OFF_Z  (NTOK*DD)
#define OFF_MU (OFF_Z + NTOK*ZD)
#define OFF_SG (OFF_MU + NTOK*ZD)

// ---------------- scratch ----------------
__device__ __nv_bfloat16 g_xz_b[(size_t)NTOK*UPK];     // [x | z] bf16
__device__ __nv_bfloat16 g_u_b[(size_t)NTOK*UPN];      // up-proj out bf16
__device__ __nv_bfloat16 g_down_b[(size_t)NTOK*DWK];   // [z|attn|mlp] bf16
__device__ __nv_bfloat16 g_upw_b[(size_t)UPN*UPK];     // bf16 up weights
__device__ __nv_bfloat16 g_dnw_b[(size_t)DD*DWK];      // bf16 down weights
__device__ __nv_bfloat16 g_xa[(size_t)NTOK*XAK];       // [x_hi | x_hi | x_lo]
__device__ __nv_bfloat16 g_wxs[(size_t)HIAFP*XAK];     // [w_hi | w_lo | w_hi] (pad rows 0)
__device__ float        g_hdnp[(size_t)NTOK*HIAFP];    // hdn pre-activation fp32
__device__ __nv_bfloat16 g_Qb[(size_t)BB*NHH*SS*DHH];  // roped Q bf16
__device__ __nv_bfloat16 g_Kb[(size_t)BB*NHH*KVL*DHH]; // registers + roped K bf16
__device__ __nv_bfloat16 g_Vb[(size_t)BB*NHH*KVS*DHH]; // registers + V bf16 (pad zero)
__device__ int   g_mask_mode;

struct RopeTab { float inv[32]; };

// ---------------- mma helpers ----------------
__device__ __forceinline__ void mma16bf(float* d, const unsigned* a, const unsigned* b) {
    asm volatile(
        "mma.sync.aligned.m16n8k16.row.col.f32.bf16.bf16.f32 "
        "{%0,%1,%2,%3}, {%4,%5,%6,%7}, {%8,%9}, {%0,%1,%2,%3};"
        : "+f"(d[0]), "+f"(d[1]), "+f"(d[2]), "+f"(d[3])
        : "r"(a[0]), "r"(a[1]), "r"(a[2]), "r"(a[3]), "r"(b[0]), "r"(b[1]));
}
__device__ __forceinline__ unsigned pack_bf(float a, float b) {
    __nv_bfloat162 h = __floats2bfloat162_rn(a, b);
    return *(unsigned*)&h;
}
__device__ __forceinline__ unsigned smem_u32(const void* p) {
    return (unsigned)__cvta_generic_to_shared(p);
}
__device__ __forceinline__ void ldmx4(unsigned* r, const __nv_bfloat16* base) {
    unsigned a = smem_u32(base);
    asm volatile("ldmatrix.sync.aligned.m8n8.x4.shared.b16 {%0,%1,%2,%3}, [%4];"
        : "=r"(r[0]), "=r"(r[1]), "=r"(r[2]), "=r"(r[3]) : "r"(a));
}

// =======================================================================
// Kernel 0: classify the storage dtype of the bool `mask` input.
// =======================================================================
__global__ void detect_mask_kernel(const unsigned char* __restrict__ p)
{
    if (threadIdx.x != 0 || blockIdx.x != 0) return;
    const unsigned int* w = (const unsigned int*)p;
    bool allf = true, anyf = false, i32ok = true;
    for (int i = 0; i < 1024; i++) {
        unsigned int v = w[i];
        if (v == 0x3F800000u) anyf = true;
        else if (v != 0u) allf = false;
        if ((v & 0xFFFFFF00u) != 0u) i32ok = false;
    }
    g_mask_mode = (allf && anyf) ? 2 : (i32ok ? 1 : 0);
}

__device__ __forceinline__ float read_mask(const unsigned char* p, int m, int mode)
{
    if (mode == 1) return ((const int*)p)[m] != 0 ? 1.f : 0.f;
    if (mode == 2) return ((const float*)p)[m] != 0.f ? 1.f : 0.f;
    return p[m] != 0 ? 1.f : 0.f;
}

// =======================================================================
// Kernel 0b: conversions
// =======================================================================
__global__ void convert_bf16_kernel(const float* __restrict__ src,
                                    __nv_bfloat16* __restrict__ dst, int n2)
{
    int i = blockIdx.x*256 + threadIdx.x;
    if (i < n2) {
        float2 v = ((const float2*)src)[i];
        ((__nv_bfloat162*)dst)[i] = __floats2bfloat162_rn(v.x, v.y);
    }
}

// iaf_wx split: g_wxs[j][0..1023]=w_hi, [1024..2047]=w_lo, [2048..3071]=w_hi
__global__ void convert_wxs_kernel(const float* __restrict__ wx)
{
    int idx = blockIdx.x*256 + threadIdx.x;      // over HIAFP*DD
    if (idx >= HIAFP*DD) return;
    int j = idx >> 10, d = idx & 1023;
    __nv_bfloat16 hi, lo;
    if (j < HIAFD) {
        float w = wx[(size_t)j*DD + d];
        hi = __float2bfloat16(w);
        lo = __float2bfloat16(w - __bfloat162float(hi));
    } else {
        hi = __float2bfloat16(0.f);
        lo = __float2bfloat16(0.f);
    }
    __nv_bfloat16* row = g_wxs + (size_t)j*XAK;
    row[d] = hi;
    row[1024 + d] = lo;
    row[2048 + d] = hi;
}

// =======================================================================
// Kernel 1a: LayerNorm per token -> bf16 x (+ split hi/lo into g_xa)
// =======================================================================
__global__ void __launch_bounds__(128) ln_kernel(
    const float* __restrict__ hs,
    const float* __restrict__ ln_w, const float* __restrict__ ln_b)
{
    __shared__ float redS[4], redQ[4], stat[2];
    const int tid = threadIdx.x, lane = tid & 31, wid = tid >> 5;
    const int m = blockIdx.x;
    const float* hp = hs + (size_t)m*DD;

    float4 xv[2];
    float s = 0.f, q = 0.f;
    #pragma unroll
    for (int k = 0; k < 2; k++) {
        xv[k] = *(const float4*)(hp + tid*4 + k*512);
        s += xv[k].x + xv[k].y + xv[k].z + xv[k].w;
        q += xv[k].x*xv[k].x + xv[k].y*xv[k].y + xv[k].z*xv[k].z + xv[k].w*xv[k].w;
    }
    #pragma unroll
    for (int o = 16; o; o >>= 1) {
        s += __shfl_down_sync(0xffffffffu, s, o);
        q += __shfl_down_sync(0xffffffffu, q, o);
    }
    if (lane == 0) { redS[wid] = s; redQ[wid] = q; }
    __syncthreads();
    if (tid == 0) {
        float S1 = redS[0]+redS[1]+redS[2]+redS[3];
        float Q1 = redQ[0]+redQ[1]+redQ[2]+redQ[3];
        float mean = S1 / (float)DD;
        float var  = Q1 / (float)DD - mean*mean;
        stat[0] = mean;
        stat[1] = rsqrtf(var + 1e-5f);
    }
    __syncthreads();
    float mean = stat[0], rstd = stat[1];
    __nv_bfloat16* xzr = g_xz_b + (size_t)m*UPK;
    __nv_bfloat16* xar = g_xa + (size_t)m*XAK;
    #pragma unroll
    for (int k = 0; k < 2; k++) {
        int d = tid*4 + k*512;
        float4 wv = *(const float4*)(ln_w + d);
        float4 bv = *(const float4*)(ln_b + d);
        float xf[4];
        xf[0] = (xv[k].x - mean)*rstd*wv.x + bv.x;
        xf[1] = (xv[k].y - mean)*rstd*wv.y + bv.y;
        xf[2] = (xv[k].z - mean)*rstd*wv.z + bv.z;
        xf[3] = (xv[k].w - mean)*rstd*wv.w + bv.w;
        #pragma unroll
        for (int e = 0; e < 4; e++) {
            __nv_bfloat16 hi = __float2bfloat16(xf[e]);
            __nv_bfloat16 lo = __float2bfloat16(xf[e] - __bfloat162float(hi));
            xzr[d + e] = hi;
            xar[d + e] = hi;
            xar[1024 + d + e] = hi;
            xar[2048 + d + e] = lo;
        }
    }
}

// =======================================================================
// Kernel 1b: z/mu/sigma from fp32 hdn-pre + noise terms (8 tokens/block)
// =======================================================================
__global__ void __launch_bounds__(128) z_kernel(
    const unsigned char* __restrict__ mask, const float* __restrict__ noise,
    const float* __restrict__ iaf_wn, const float* __restrict__ iaf_w2,
    float* __restrict__ out)
{
    __shared__ float ns[8][ZD];
    __shared__ float hdn[8][HIAFD];
    __shared__ float zps[8][2*ZD];
    __shared__ float fmv[8];
    const int tid = threadIdx.x;
    const int m0 = blockIdx.x * 8;
    const int mmode = g_mask_mode;

    {
        int t = tid >> 5, i = tid & 31;
        float fm = read_mask(mask, m0 + t, mmode);
        ns[t][i] = noise[(size_t)(m0 + t)*ZD + i] * fm;
        ns[t + 4][i] = noise[(size_t)(m0 + t + 4)*ZD + i] *
                       read_mask(mask, m0 + t + 4, mmode);
        if (i == 0) {
            fmv[t] = fm;
            fmv[t + 4] = read_mask(mask, m0 + t + 4, mmode);
        }
    }
    __syncthreads();

    {
        int j = tid;
        float acc[8];
        #pragma unroll
        for (int t = 0; t < 8; t++)
            acc[t] = g_hdnp[(size_t)(m0 + t)*HIAFP + j];
        int dm = j % 31;                 // M1[j][i] = (i <= j%31)
        const float* wn = iaf_wn + (size_t)j*ZD;
        for (int i = 0; i <= dm; i++) {
            float w = wn[i];
            #pragma unroll
            for (int t = 0; t < 8; t++) acc[t] += ns[t][i]*w;
        }
        #pragma unroll
        for (int t = 0; t < 8; t++) {
            float v = acc[t];
            hdn[t][j] = v / (1.f + __expf(-v));
        }
    }
    __syncthreads();

    if (tid < 64) {
        int o = tid, lim = o & 31;       // M2[o][j] = (j%31 < o%32)
        float acc[8];
        #pragma unroll
        for (int t = 0; t < 8; t++) acc[t] = 0.f;
        const float* w2 = iaf_w2 + (size_t)o*HIAFD;
        for (int j = 0; j < HIAFD; j++) {
            if ((j % 31) < lim) {
                float w = w2[j];
                #pragma unroll
                for (int t = 0; t < 8; t++) acc[t] += hdn[t][j]*w;
            }
        }
        #pragma unroll
        for (int t = 0; t < 8; t++) zps[t][o] = fmv[t]*ZSCALE*acc[t];
    }
    __syncthreads();

    for (int idx = tid; idx < 8*ZD; idx += 128) {
        int t = idx >> 5, i = idx & 31;
        int m = m0 + t;
        float mu = zps[t][i];
        float ls = zps[t][ZD + i] + SPSHIFT;
        float sg = (ls > 20.f) ? ls : log1pf(expf(ls));
        float z  = mu + sg*ns[t][i];
        g_xz_b[(size_t)m*UPK + DD + i] = __float2bfloat16(z);
        g_down_b[(size_t)m*DWK + i]    = __float2bfloat16(z);
        out[OFF_Z  + (size_t)m*ZD + i] = z;
        out[OFF_MU + (size_t)m*ZD + i] = mu;
        out[OFF_SG + (size_t)m*ZD + i] = sg;
    }
}

// =======================================================================
// Kernel 2: BF16 GEMM 128x256x32, cp.async double-buffered, ldmatrix frags.
//   EPI=0: C bf16;  EPI=1: C fp32 residual;  EPI=2: C fp32 plain
// =======================================================================
#define APITCH 40

__device__ __forceinline__ void bgemm_prefetch(
    const __nv_bfloat16* __restrict__ A, const __nv_bfloat16* __restrict__ B,
    __nv_bfloat16* As, __nv_bfloat16* Bs, int bm, int bn, int lda, int ldb, int k0, int tid)
{
    #pragma unroll
    for (int j = 0; j < 2; j++) {
        int idx = tid + j*256, r = idx >> 2, c = idx & 3;
        unsigned d = smem_u32(As + r*APITCH + c*8);
        asm volatile("cp.async.ca.shared.global [%0], [%1], 16;"
                     :: "r"(d), "l"(A + (size_t)(bm + r)*lda + k0 + c*8));
    }
    #pragma unroll
    for (int j = 0; j < 4; j++) {
        int idx = tid + j*256, r = idx >> 2, c = idx & 3;
        unsigned d = smem_u32(Bs + r*APITCH + c*8);
        asm volatile("cp.async.ca.shared.global [%0], [%1], 16;"
                     :: "r"(d), "l"(B + (size_t)(bn + r)*ldb + k0 + c*8));
    }
}

template<int EPI>
__global__ void __launch_bounds__(256) bf16_gemm_nt(
    const __nv_bfloat16* __restrict__ A, const __nv_bfloat16* __restrict__ Bw, void* Cp,
    int M, int N, int K, int lda, int ldb,
    const float* __restrict__ addsrc, const float* __restrict__ alphap)
{
    extern __shared__ __nv_bfloat16 smb[];
    __nv_bfloat16* Asb[2] = { smb, smb + 128*APITCH };
    __nv_bfloat16* Bsb[2] = { smb + 2*128*APITCH, smb + 2*128*APITCH + 256*APITCH };
    const int tid = threadIdx.x;
    const int lane = tid & 31, wid = tid >> 5;
    const int g = lane >> 2, t = lane & 3;
    const int l16 = lane & 15, lhi = (lane >> 4) * 8;
    const int wm = (wid >> 2) * 64, wn = (wid & 3) * 64;
    const int bm = blockIdx.y * 128, bn = blockIdx.x * 256;

    float acc[4][8][4];
    #pragma unroll
    for (int mi = 0; mi < 4; mi++)
        #pragma unroll
        for (int ni = 0; ni < 8; ni++)
            #pragma unroll
            for (int e = 0; e < 4; e++) acc[mi][ni][e] = 0.f;

    const int KT = K / 32;
    bgemm_prefetch(A, Bw, Asb[0], Bsb[0], bm, bn, lda, ldb, 0, tid);
    asm volatile("cp.async.commit_group;");

    for (int kt = 0; kt < KT; kt++) {
        const int buf = kt & 1;
        if (kt + 1 < KT) {
            bgemm_prefetch(A, Bw, Asb[buf^1], Bsb[buf^1], bm, bn, lda, ldb, (kt+1)*32, tid);
            asm volatile("cp.async.commit_group;");
            asm volatile("cp.async.wait_group 1;");
        } else {
            asm volatile("cp.async.wait_group 0;");
        }
        __syncthreads();
        const __nv_bfloat16* As = Asb[buf];
        const __nv_bfloat16* Bs = Bsb[buf];
        #pragma unroll
        for (int ks = 0; ks < 32; ks += 16) {
            unsigned a[4][4], b[8][2];
            #pragma unroll
            for (int mi = 0; mi < 4; mi++)
                ldmx4(a[mi], As + (wm + mi*16 + l16)*APITCH + ks + lhi);
            #pragma unroll
            for (int np = 0; np < 4; np++) {
                unsigned r[4];
                ldmx4(r, Bs + (wn + np*16 + l16)*APITCH + ks + lhi);
                b[2*np][0] = r[0]; b[2*np + 1][0] = r[1];
                b[2*np][1] = r[2]; b[2*np + 1][1] = r[3];
            }
            #pragma unroll
            for (int mi = 0; mi < 4; mi++)
                #pragma unroll
                for (int ni = 0; ni < 8; ni++)
                    mma16bf(acc[mi][ni], a[mi], b[ni]);
        }
        __syncthreads();
    }

    float alpha = (EPI == 1) ? *alphap : 0.f;
    #pragma unroll
    for (int mi = 0; mi < 4; mi++) {
        int r0 = bm + wm + mi*16 + g;
        #pragma unroll
        for (int ni = 0; ni < 8; ni++) {
            int c0 = bn + wn + ni*8 + 2*t;
            #pragma unroll
            for (int h = 0; h < 2; h++) {
                int row = r0 + 8*h;
                size_t o = (size_t)row*N + c0;
                float v0 = acc[mi][ni][2*h], v1 = acc[mi][ni][2*h + 1];
                if (EPI == 1) {
                    float* C = (float*)Cp;
                    C[o]   = addsrc[o]   + alpha*v0;
                    C[o+1] = addsrc[o+1] + alpha*v1;
                } else if (EPI == 2) {
                    float* C = (float*)Cp;
                    C[o]   = v0;
                    C[o+1] = v1;
                } else {
                    __nv_bfloat16* C = (__nv_bfloat16*)Cp;
                    *(__nv_bfloat162*)(C + o) = __floats2bfloat162_rn(v0, v1);
                }
            }
        }
    }
}

// =======================================================================
// Kernel 3: QKV prep — 8 tokens/block, bf16 u reads, RoPE, bf16 QKV out
// =======================================================================
__global__ void __launch_bounds__(256) prep_qkv(
    const float* __restrict__ next_noise, const float* __restrict__ iaf_up_w, RopeTab tab)
{
    __shared__ float nn[8][ZD];
    __shared__ float kadds[8][256], vadds[8][256];
    const int tid = threadIdx.x;
    const int m0 = blockIdx.x * 8;

    {
        int t8 = tid >> 5, i = tid & 31;
        nn[t8][i] = next_noise[(size_t)(m0 + t8)*ZD + i];
    }
    __syncthreads();
    {
        const float* wk = iaf_up_w + (size_t)tid*ZD;
        const float* wv = iaf_up_w + (size_t)(QKVD + tid)*ZD;
        float ka[8], va[8];
        #pragma unroll
        for (int u = 0; u < 8; u++) { ka[u] = 0.f; va[u] = 0.f; }
        #pragma unroll 4
        for (int i = 0; i < ZD; i++) {
            float wki = wk[i], wvi = wv[i];
            #pragma unroll
            for (int u = 0; u < 8; u++) {
                ka[u] += nn[u][i]*wki;
                va[u] += nn[u][i]*wvi;
            }
        }
        #pragma unroll
        for (int u = 0; u < 8; u++) { kadds[u][tid] = ka[u]; vadds[u][tid] = va[u]; }
    }
    __syncthreads();

    const int dd = tid & 31;
    for (int u = 0; u < 8; u++) {
        int m = m0 + u;
        int b = m >> 11, spos = m & 2047;
        const __nv_bfloat16* um = g_u_b + (size_t)m*UPN;
        float ang = (float)spos * tab.inv[dd];
        float c, sn; sincosf(ang, &sn, &c);
        #pragma unroll
        for (int pp = 0; pp < 2; pp++) {
            int p = tid + pp*256;            // 0..511
            int hh = p >> 5;
            int i1 = hh*DHH + dd, i2 = i1 + 32;
            float q1 = __bfloat162float(um[i1]);
            float q2 = __bfloat162float(um[i2]);
            size_t qo = (((size_t)(b*NHH + hh))*SS + spos)*DHH;
            g_Qb[qo + dd]      = __float2bfloat16(q1*c - q2*sn);
            g_Qb[qo + 32 + dd] = __float2bfloat16(q2*c + q1*sn);
            float k1 = __bfloat162float(um[QKVD + i1]) + (i1 < 256 ? kadds[u][i1] : 0.f);
            float k2 = __bfloat162float(um[QKVD + i2]) + (i2 < 256 ? kadds[u][i2] : 0.f);
            size_t ko = (((size_t)(b*NHH + hh))*KVL + RG + spos)*DHH;
            g_Kb[ko + dd]      = __float2bfloat16(k1*c - k2*sn);
            g_Kb[ko + 32 + dd] = __float2bfloat16(k2*c + k1*sn);
        }
        #pragma unroll
        for (int pp = 0; pp < 4; pp++) {
            int p = tid + pp*256;            // 0..1023
            int hh = p >> 6;
            float vv = __bfloat162float(um[2*QKVD + p]) + (p < 256 ? vadds[u][p] : 0.f);
            g_Vb[(((size_t)(b*NHH + hh))*KVS + RG + spos)*DHH + (p & 63)] = __float2bfloat16(vv);
        }
    }
}

// register tokens K/V fill + V pad-row zeroing
__global__ void regfill_kernel(const float* __restrict__ reg_k, const float* __restrict__ reg_v)
{
    int bh = blockIdx.x, hh = bh & 15;
    int j = threadIdx.x >> 6, d = threadIdx.x & 63;
    g_Kb[((size_t)bh*KVL + j)*DHH + d] = __float2bfloat16(reg_k[((size_t)j*NHH + hh)*DHH + d]);
    g_Vb[((size_t)bh*KVS + j)*DHH + d] = __float2bfloat16(reg_v[((size_t)j*NHH + hh)*DHH + d]);
    for (int idx = threadIdx.x; idx < (KVS - KVL)*DHH; idx += blockDim.x)
        g_Vb[((size_t)bh*KVS + KVL)*DHH + idx] = __float2bfloat16(0.f);
}

// =======================================================================
// Kernel 4: FLASH attention, all-bf16 mma (m16n8k16), no P shuffles
// =======================================================================
#define KSPb 72     // Ks pitch (bf16), rows = q/k tokens
#define VSPb 134    // Vs pitch (bf16), rows = head dim (n-major, transposed)
#define FLASH_SMEM (128*KSPb*2 + 64*VSPb*2)   // 35584 B

__global__ void __launch_bounds__(256) flash_kernel(const float* __restrict__ attn_mask)
{
    extern __shared__ __nv_bfloat16 sfb[];
    __nv_bfloat16* Ks = sfb;
    __nv_bfloat16* Vs = sfb + 128*KSPb;
    const int tid = threadIdx.x, lane = tid & 31, w = tid >> 5;
    const int g = lane >> 2, t = lane & 3;
    const int bh = blockIdx.y, b = bh >> 4, hh = bh & 15;
    const int bm = blockIdx.x * 128;
    const __nv_bfloat16* Qb = g_Qb + (size_t)bh*SS*DHH;
    const __nv_bfloat16* Kb = g_Kb + (size_t)bh*KVL*DHH;
    const __nv_bfloat16* Vb = g_Vb + (size_t)bh*KVS*DHH;

    // stage Q tile (bf16 copy), gather bf16 A-frags
    #pragma unroll
    for (int j = 0; j < 4; j++) {
        int idx = tid + j*256, r = idx >> 3, c8 = (idx & 7)*8;
        *(uint4*)(Ks + r*KSPb + c8) = *(const uint4*)(Qb + (size_t)(bm + r)*DHH + c8);
    }
    __syncthreads();
    unsigned aQ[4][4];
    #pragma unroll
    for (int ks = 0; ks < 4; ks++) {
        const __nv_bfloat16* p0 = Ks + (w*16 + g)*KSPb + ks*16 + 2*t;
        aQ[ks][0] = *(const unsigned*)(p0);
        aQ[ks][1] = *(const unsigned*)(p0 + 8*KSPb);
        aQ[ks][2] = *(const unsigned*)(p0 + 8);
        aQ[ks][3] = *(const unsigned*)(p0 + 8*KSPb + 8);
    }
    __syncthreads();

    float accO[8][4];
    #pragma unroll
    for (int vn = 0; vn < 8; vn++)
        #pragma unroll
        for (int e = 0; e < 4; e++) accO[vn][e] = 0.f;
    float mrow0 = -1e30f, mrow1 = -1e30f, lrow0 = 0.f, lrow1 = 0.f;

    const int gi0 = bm + w*16 + g, gi1 = gi0 + 8;
    const float* am0 = attn_mask + ((size_t)b*SS + gi0)*SS;
    const float* am1 = attn_mask + ((size_t)b*SS + gi1)*SS;
    const bool iafh = (hh < NIAFH);

    for (int j0 = 0; j0 < KVL; j0 += 128) {
        #pragma unroll
        for (int j = 0; j < 4; j++) {
            int idx = tid + j*256, r = idx >> 3, c8 = (idx & 7)*8;
            uint4 v = (j0 + r < KVL)
                    ? *(const uint4*)(Kb + (size_t)(j0 + r)*DHH + c8)
                    : make_uint4(0u, 0u, 0u, 0u);
            *(uint4*)(Ks + r*KSPb + c8) = v;
        }
        #pragma unroll
        for (int j = 0; j < 4; j++) {
            int idx = tid + j*256, r = idx >> 3, c8 = (idx & 7)*8;
            uint4 v = (j0 + r < KVL)
                    ? *(const uint4*)(Vb + (size_t)(j0 + r)*DHH + c8)
                    : make_uint4(0u, 0u, 0u, 0u);
            __nv_bfloat16 h[8];
            *(uint4*)h = v;
            #pragma unroll
            for (int i = 0; i < 8; i++)
                Vs[(c8 + i)*VSPb + r] = h[i];
        }
        __syncthreads();

        float s[16][4];
        #pragma unroll
        for (int nt = 0; nt < 16; nt++)
            #pragma unroll
            for (int e = 0; e < 4; e++) s[nt][e] = 0.f;
        #pragma unroll
        for (int ks = 0; ks < 4; ks++) {
            #pragma unroll
            for (int nt = 0; nt < 16; nt++) {
                unsigned bb[2];
                const __nv_bfloat16* pn = Ks + (nt*8 + g)*KSPb + ks*16 + 2*t;
                bb[0] = *(const unsigned*)(pn);
                bb[1] = *(const unsigned*)(pn + 8);
                mma16bf(s[nt], aQ[ks], bb);
            }
        }

        float tmax0 = -1e30f, tmax1 = -1e30f;
        #pragma unroll
        for (int nt = 0; nt < 16; nt++) {
            int colbase = j0 + nt*8;
            if (colbase >= KVL) {
                s[nt][0] = s[nt][1] = s[nt][2] = s[nt][3] = -1e30f;
            } else if (colbase < RG) {
                s[nt][0] *= 0.125f; s[nt][1] *= 0.125f;
                s[nt][2] *= 0.125f; s[nt][3] *= 0.125f;
            } else {
                int js = colbase + 2*t - RG;
                float2 a0 = *(const float2*)(am0 + js);
                float2 a1 = *(const float2*)(am1 + js);
                float mk00 = a0.x, mk01 = a0.y, mk10 = a1.x, mk11 = a1.y;
                if (iafh) {
                    if (js     >= gi0) mk00 += NEGV;
                    if (js + 1 >= gi0) mk01 += NEGV;
                    if (js     >= gi1) mk10 += NEGV;
                    if (js + 1 >= gi1) mk11 += NEGV;
                }
                s[nt][0] = s[nt][0]*0.125f + mk00;
                s[nt][1] = s[nt][1]*0.125f + mk01;
                s[nt][2] = s[nt][2]*0.125f + mk10;
                s[nt][3] = s[nt][3]*0.125f + mk11;
            }
            tmax0 = fmaxf(tmax0, fmaxf(s[nt][0], s[nt][1]));
            tmax1 = fmaxf(tmax1, fmaxf(s[nt][2], s[nt][3]));
        }
        tmax0 = fmaxf(tmax0, __shfl_xor_sync(0xffffffffu, tmax0, 1));
        tmax0 = fmaxf(tmax0, __shfl_xor_sync(0xffffffffu, tmax0, 2));
        tmax1 = fmaxf(tmax1, __shfl_xor_sync(0xffffffffu, tmax1, 1));
        tmax1 = fmaxf(tmax1, __shfl_xor_sync(0xffffffffu, tmax1, 2));

        float newm0 = fmaxf(mrow0, tmax0);
        float newm1 = fmaxf(mrow1, tmax1);
        float sc0 = __expf(mrow0 - newm0);
        float sc1 = __expf(mrow1 - newm1);
        float rs0 = 0.f, rs1 = 0.f;
        #pragma unroll
        for (int nt = 0; nt < 16; nt++) {
            float p0 = __expf(s[nt][0] - newm0);
            float p1 = __expf(s[nt][1] - newm0);
            float p2 = __expf(s[nt][2] - newm1);
            float p3 = __expf(s[nt][3] - newm1);
            s[nt][0] = p0; s[nt][1] = p1; s[nt][2] = p2; s[nt][3] = p3;
            rs0 += p0 + p1; rs1 += p2 + p3;
        }
        rs0 += __shfl_xor_sync(0xffffffffu, rs0, 1);
        rs0 += __shfl_xor_sync(0xffffffffu, rs0, 2);
        rs1 += __shfl_xor_sync(0xffffffffu, rs1, 1);
        rs1 += __shfl_xor_sync(0xffffffffu, rs1, 2);
        lrow0 = lrow0*sc0 + rs0;
        lrow1 = lrow1*sc1 + rs1;
        mrow0 = newm0; mrow1 = newm1;
        #pragma unroll
        for (int vn = 0; vn < 8; vn++) {
            accO[vn][0] *= sc0; accO[vn][1] *= sc0;
            accO[vn][2] *= sc1; accO[vn][3] *= sc1;
        }

        #pragma unroll
        for (int ks = 0; ks < 8; ks++) {
            unsigned aP[4];
            aP[0] = pack_bf(s[2*ks][0],     s[2*ks][1]);
            aP[1] = pack_bf(s[2*ks][2],     s[2*ks][3]);
            aP[2] = pack_bf(s[2*ks + 1][0], s[2*ks + 1][1]);
            aP[3] = pack_bf(s[2*ks + 1][2], s[2*ks + 1][3]);
            #pragma unroll
            for (int vn = 0; vn < 8; vn++) {
                unsigned bb[2];
                const __nv_bfloat16* pv = Vs + (vn*8 + g)*VSPb + ks*16 + 2*t;
                bb[0] = *(const unsigned*)(pv);
                bb[1] = *(const unsigned*)(pv + 8);
                mma16bf(accO[vn], aP, bb);
            }
        }
        __syncthreads();
    }

    float inv0 = 1.f / lrow0, inv1 = 1.f / lrow1;
    int row0 = b*SS + gi0, row1 = b*SS + gi1;
    #pragma unroll
    for (int vn = 0; vn < 8; vn++) {
        int n = vn*8 + 2*t;
        *(__nv_bfloat162*)(g_down_b + (size_t)row0*DWK + ZD + hh*DHH + n) =
            __floats2bfloat162_rn(accO[vn][0]*inv0, accO[vn][1]*inv0);
        *(__nv_bfloat162*)(g_down_b + (size_t)row1*DWK + ZD + hh*DHH + n) =
            __floats2bfloat162_rn(accO[vn][2]*inv1, accO[vn][3]*inv1);
    }
}

// =======================================================================
// Kernel 5: mlp = silu(gate)*val into g_down_b (bf16x2, coalesced)
// =======================================================================
__global__ void __launch_bounds__(256) mlp_kernel()
{
    size_t idx = (size_t)blockIdx.x*256 + threadIdx.x;   // over NTOK*MLPD/2
    int m = (int)(idx >> 11);
    int jj = (int)(idx & 2047);
    const __nv_bfloat162* gp = (const __nv_bfloat162*)(g_u_b + (size_t)m*UPN + 3*QKVD) + jj;
    const __nv_bfloat162* vp = (const __nv_bfloat162*)(g_u_b + (size_t)m*UPN + 3*QKVD + MLPD) + jj;
    float2 gv = __bfloat1622float2(*gp);
    float2 vv = __bfloat1622float2(*vp);
    float r0 = gv.x / (1.f + __expf(-gv.x)) * vv.x;
    float r1 = gv.y / (1.f + __expf(-gv.y)) * vv.y;
    *((__nv_bfloat162*)(g_down_b + (size_t)m*DWK + ZD + QKVD) + jj) =
        __floats2bfloat162_rn(r0, r1);
}

// =======================================================================
// launch
// =======================================================================
extern "C" void kernel_launch(void* const* d_in, const int* in_sizes, int n_in,
                              void* d_out, int out_size)
{
    const float* hs          = (const float*)d_in[0];
    const unsigned char* msk = (const unsigned char*)d_in[1];
    const float* noise       = (const float*)d_in[2];
    const float* next_noise  = (const float*)d_in[3];
    const float* attn_mask   = (const float*)d_in[4];
    const float* ln_w        = (const float*)d_in[5];
    const float* ln_b        = (const float*)d_in[6];
    const float* alpha       = (const float*)d_in[7];
    const float* iaf_wx      = (const float*)d_in[8];
    const float* iaf_wn      = (const float*)d_in[9];
    const float* iaf_w2      = (const float*)d_in[10];
    const float* up_w        = (const float*)d_in[11];
    const float* iaf_up_w    = (const float*)d_in[12];
    const float* down_w      = (const float*)d_in[13];
    const float* reg_k       = (const float*)d_in[14];
    const float* reg_v       = (const float*)d_in[15];
    float* out = (float*)d_out;

    __nv_bfloat16 *p_xz, *p_u, *p_down, *p_upw, *p_dnw, *p_xa, *p_wxs;
    float *p_hdnp;
    cudaGetSymbolAddress((void**)&p_xz, g_xz_b);
    cudaGetSymbolAddress((void**)&p_u, g_u_b);
    cudaGetSymbolAddress((void**)&p_down, g_down_b);
    cudaGetSymbolAddress((void**)&p_upw, g_upw_b);
    cudaGetSymbolAddress((void**)&p_dnw, g_dnw_b);
    cudaGetSymbolAddress((void**)&p_xa, g_xa);
    cudaGetSymbolAddress((void**)&p_wxs, g_wxs);
    cudaGetSymbolAddress((void**)&p_hdnp, g_hdnp);

    const int GEMM_SMEM = (2*128 + 2*256)*APITCH*2;   // 61440
    (void)cudaFuncSetAttribute(bf16_gemm_nt<0>, cudaFuncAttributeMaxDynamicSharedMemorySize, GEMM_SMEM);
    (void)cudaFuncSetAttribute(bf16_gemm_nt<1>, cudaFuncAttributeMaxDynamicSharedMemorySize, GEMM_SMEM);
    (void)cudaFuncSetAttribute(bf16_gemm_nt<2>, cudaFuncAttributeMaxDynamicSharedMemorySize, GEMM_SMEM);
    (void)cudaFuncSetAttribute(flash_kernel, cudaFuncAttributeMaxDynamicSharedMemorySize, FLASH_SMEM);

    RopeTab rt;
    for (int d = 0; d < 32; d++) {
        float pw = powf(10000.f, (float)(2*d) / 64.f);
        rt.inv[d] = 1.f / pw;
    }

    detect_mask_kernel<<<1, 32>>>(msk);

    // weight conversions (fp32 -> bf16)
    convert_bf16_kernel<<<(UPN*UPK/2 + 255)/256, 256>>>(up_w, p_upw, UPN*UPK/2);
    convert_bf16_kernel<<<(DD*DWK/2 + 255)/256, 256>>>(down_w, p_dnw, DD*DWK/2);
    convert_wxs_kernel<<<(HIAFP*DD + 255)/256, 256>>>(iaf_wx);

    // token path: LN -> split-precision iaf_wx GEMM (fp32 out) -> z/mu/sigma
    ln_kernel<<<NTOK, 128>>>(hs, ln_w, ln_b);
    bf16_gemm_nt<2><<<dim3(HIAFP/256, NTOK/128), 256, GEMM_SMEM>>>(
        p_xa, p_wxs, p_hdnp, NTOK, HIAFP, XAK, XAK, XAK, nullptr, nullptr);
    z_kernel<<<NTOK/8, 128>>>(msk, noise, iaf_wn, iaf_w2, out);

    bf16_gemm_nt<0><<<dim3(UPN/256, NTOK/128), 256, GEMM_SMEM>>>(
        p_xz, p_upw, p_u, NTOK, UPN, UPK, UPK, UPK, nullptr, nullptr);

    prep_qkv<<<NTOK/8, 256>>>(next_noise, iaf_up_w, rt);
    regfill_kernel<<<BB*NHH, 512>>>(reg_k, reg_v);

    flash_kernel<<<dim3(SS/128, BB*NHH), 256, FLASH_SMEM>>>(attn_mask);

    mlp_kernel<<<(NTOK*MLPD/2)/256, 256>>>();

    bf16_gemm_nt<1><<<dim3(DD/256, NTOK/128), 256, GEMM_SMEM>>>(
        p_down, p_dnw, out, NTOK, DD, DWK, DWK, DWK, hs, alpha);
}